// round 12
// baseline (speedup 1.0000x reference)
#include <cuda_runtime.h>
#include <cuda_fp16.h>
#include <stdint.h>

typedef unsigned long long u64;

#define LSEQ 2048
#define BATCH 8
#define NH 4
#define NBH (BATCH*NH)      // 32
#define HDIM 64
#define DM 256
#define DOUT 1024
#define NTOK (BATCH*LSEQ)   // 16384
#define SCALE 0.090168440055560214f   // log2(e)/16

// ---------------- device scratch (no runtime alloc allowed) ----------------
__device__ __align__(16) unsigned short g_Qh[(size_t)NBH*LSEQ*HDIM];  // fp16 Q (unscaled)
__device__ __align__(16) unsigned short g_Kh[(size_t)NBH*LSEQ*HDIM];  // fp16 K
__device__ __align__(16) unsigned short g_Vth[(size_t)NBH*HDIM*LSEQ]; // fp16 [bh][d][l]
__device__ __align__(16) unsigned short g_xh[(size_t)NTOK*DM];        // fp16 x
__device__ __align__(16) unsigned short g_CXh[(size_t)NTOK*DM];       // fp16 ctx [b,l,h*64+j]
#define WROWS (3*DM + DOUT)   // 1792 rows of W^T (qkv then out)
__device__ __align__(16) unsigned short g_Wh[(size_t)WROWS*DM];       // fp16 W^T [n][k]

// ---------------- scalar helpers ----------------
__device__ __forceinline__ uint32_t hpack(float a, float b){
    __half2 h2 = __floats2half2_rn(a, b);
    return *(uint32_t*)&h2;
}
__device__ __forceinline__ float ex2f(float x){
    float r; asm("ex2.approx.f32 %0,%1;":"=f"(r):"f"(x)); return r; }

// ---------------- warp-MMA + cp.async primitives ----------------
__device__ __forceinline__ void ldsm4(uint32_t &r0, uint32_t &r1, uint32_t &r2, uint32_t &r3, uint32_t addr){
    asm volatile("ldmatrix.sync.aligned.m8n8.x4.shared.b16 {%0,%1,%2,%3},[%4];"
        : "=r"(r0),"=r"(r1),"=r"(r2),"=r"(r3) : "r"(addr));
}
__device__ __forceinline__ void mma_f16(float* d, const uint32_t* a, uint32_t b0, uint32_t b1){
    asm volatile("mma.sync.aligned.m16n8k16.row.col.f32.f16.f16.f32 "
        "{%0,%1,%2,%3},{%4,%5,%6,%7},{%8,%9},{%0,%1,%2,%3};"
        : "+f"(d[0]),"+f"(d[1]),"+f"(d[2]),"+f"(d[3])
        : "r"(a[0]),"r"(a[1]),"r"(a[2]),"r"(a[3]),"r"(b0),"r"(b1));
}
__device__ __forceinline__ uint32_t swz(uint32_t o){ return o ^ ((o>>3)&0x70u); }
__device__ __forceinline__ void cpa16(uint32_t saddr, const void* g){
    asm volatile("cp.async.cg.shared.global [%0],[%1],16;"::"r"(saddr),"l"(g));
}
#define CPCOMMIT() asm volatile("cp.async.commit_group;":::"memory")
template<int N> __device__ __forceinline__ void cpwait(){
    asm volatile("cp.async.wait_group %0;"::"n"(N):"memory");
}

// ===========================================================================
// Prep kernels
// ===========================================================================
__global__ __launch_bounds__(256)
void xcvt(const float* __restrict__ x)
{
    uint32_t* xh = (uint32_t*)g_xh;
    size_t p0 = (size_t)blockIdx.x*1024 + threadIdx.x;
    #pragma unroll
    for (int i=0;i<4;i++){
        size_t p = p0 + (size_t)i*256;
        float2 v = ((const float2*)x)[p];
        xh[p] = hpack(v.x, v.y);
    }
}

// W^T convert (fp16). qkv (3 x 256x256) then Wo (256x1024) -> [n][k].
__global__ __launch_bounds__(256)
void wsplit(const float* __restrict__ Wq, const float* __restrict__ Wk,
            const float* __restrict__ Wv, const float* __restrict__ Wo)
{
    __shared__ float ts[64][65];
    const int tid = threadIdx.x;
    int bx = blockIdx.x;
    const float* W; int N, kt0, nt0, rowbase;
    if (bx < 48) {
        int mat = bx/16, t = bx%16;
        W = (mat==0)?Wq:(mat==1)?Wk:Wv; N = DM;
        kt0 = (t>>2)<<6; nt0 = (t&3)<<6; rowbase = mat*DM + nt0;
    } else {
        bx -= 48;
        W = Wo; N = DOUT;
        kt0 = (bx&3)<<6; nt0 = (bx>>2)<<6; rowbase = 3*DM + nt0;
    }
    #pragma unroll
    for (int i=0;i<16;i++){
        int e = tid + (i<<8);
        int k = e>>6, n = e&63;
        ts[n][k] = W[(size_t)(kt0+k)*N + nt0 + n];
    }
    __syncthreads();
    uint32_t* wh = (uint32_t*)g_Wh;
    #pragma unroll
    for (int i=0;i<8;i++){
        int e = tid + (i<<8);
        int n = e>>5, kp = e&31;
        size_t o = (size_t)(rowbase+n)*(DM/2) + (kt0>>1) + kp;
        wh[o] = hpack(ts[n][kp*2], ts[n][kp*2+1]);
    }
}

// ===========================================================================
// HMMA GEMM core, templated on N-tile (64 or 128). 128(M) rows, K=256 in 4 chunks.
// Buffer: A 16K + W (N*256B). Double-buffered.
// ===========================================================================
template<int NT> struct GOff {
    static constexpr uint32_t AH  = 0;
    static constexpr uint32_t WH  = 16384;
    static constexpr uint32_t BUF = 16384u + (uint32_t)NT*256u;
};

template<int NT>
__device__ __forceinline__ void gemm_stage(
    uint32_t sb, uint32_t buf, const char* gah, int row0, int wrow, int kt)
{
    const int tid = threadIdx.x;
    const char* gwh = (const char*)g_Wh;
    #pragma unroll
    for (int i=0;i<4;i++){
        int idx = tid + (i<<8);
        int row = idx>>3, j = idx&7;
        const char* s = gah + (size_t)(row0+row)*512 + kt*128 + j*16;
        cpa16(sb + buf + GOff<NT>::AH + swz(row*128 + j*16), s);
    }
    #pragma unroll
    for (int i=0;i<NT/32;i++){
        int idx = tid + (i<<8);
        int row = idx>>3, j = idx&7;
        const char* s = gwh + (size_t)(wrow+row)*512 + kt*128 + j*16;
        cpa16(sb + buf + GOff<NT>::WH + swz(row*128 + j*16), s);
    }
}

template<int NT>
__device__ __forceinline__ void gemm_mma_core(
    uint32_t sb, const char* gah, int row0, int wrow, float (&o)[NT/8][4])
{
    const int tid = threadIdx.x, lane = tid&31, wid = tid>>5;
    const uint32_t lrow = (uint32_t)(lane&15)*128 + (uint32_t)(lane&16);

    gemm_stage<NT>(sb, 0, gah, row0, wrow, 0);
    CPCOMMIT();

    #pragma unroll 1
    for (int kt = 0; kt < 4; kt++) {
        const uint32_t buf = (kt&1) ? GOff<NT>::BUF : 0;
        if (kt < 3) {
            gemm_stage<NT>(sb, (kt&1)?0:GOff<NT>::BUF, gah, row0, wrow, kt+1);
            CPCOMMIT();
            cpwait<1>();
        } else {
            cpwait<0>();
        }
        __syncthreads();

        const uint32_t abase = sb + buf + (uint32_t)(wid<<4)*128;
        #pragma unroll
        for (int c=0;c<4;c++){
            uint32_t ah[4];
            ldsm4(ah[0],ah[1],ah[2],ah[3], abase + GOff<NT>::AH + swz(lrow + c*32));
            #pragma unroll
            for (int p=0;p<NT/16;p++){
                uint32_t wh0,wh1,wh2,wh3;
                uint32_t boff = swz((uint32_t)(p<<11) + lrow + c*32);
                ldsm4(wh0,wh1,wh2,wh3, sb + buf + GOff<NT>::WH + boff);
                mma_f16(o[2*p],   ah, wh0, wh2);
                mma_f16(o[2*p+1], ah, wh1, wh3);
            }
        }
        __syncthreads();
    }
}

#define GEMM_SMEM_QKV (2*(16384+64*256))     // 81920? no: 64*256=16384 -> 65536
#define GEMM_SMEM_OUT (2*(16384+128*256))    // 2*49152 = 98304

// QKV projection: Q/K -> fp16 [bh][l][d]; V -> fp16 transposed [bh][d][l] (fused)
__global__ __launch_bounds__(256,2)
void gemm_qkv(const float* __restrict__ bq, const float* __restrict__ bk,
              const float* __restrict__ bv)
{
    extern __shared__ __align__(128) char smem[];
    const uint32_t sb = (uint32_t)__cvta_generic_to_shared(smem);
    const int tid = threadIdx.x, lane = tid&31, wid = tid>>5;
    const int row0 = blockIdx.x<<7;
    const int yy = blockIdx.y, mat = yy>>2, h = yy&3;
    const int col0 = h<<6;
    const float* bias = (mat==0)?bq:(mat==1)?bk:bv;
    const int wrow = mat*DM + col0;

    float o[8][4];
    #pragma unroll
    for (int j=0;j<8;j++){ o[j][0]=0.f;o[j][1]=0.f;o[j][2]=0.f;o[j][3]=0.f; }

    gemm_mma_core<64>(sb, (const char*)g_xh, row0, wrow, o);

    const int r = row0 + (wid<<4) + (lane>>2);
    const int b = r>>11, l = r&2047;
    const int bh = b*NH + h;

    if (mat < 2) {
        uint32_t* dh = (uint32_t*)((mat==0)?g_Qh:g_Kh);
        #pragma unroll
        for (int j=0;j<8;j++){
            int dcol = 8*j + ((lane&3)<<1);
            float2 bb = *(const float2*)&bias[col0 + dcol];
            size_t p0 = (((size_t)bh*LSEQ + l)*HDIM + dcol)>>1;
            size_t p1 = (((size_t)bh*LSEQ + l+8)*HDIM + dcol)>>1;
            dh[p0] = hpack(o[j][0]+bb.x, o[j][1]+bb.y);
            dh[p1] = hpack(o[j][2]+bb.x, o[j][3]+bb.y);
        }
    } else {
        // fused V transpose: stage fp16 into smem vt[64 d][128 l] then coalesced out
        __half* vt = (__half*)smem;      // 64*128 halves = 16 KB
        const int lloc = (wid<<4) + (lane>>2);
        #pragma unroll
        for (int j=0;j<8;j++){
            int dcol = 8*j + ((lane&3)<<1);
            float2 bb = *(const float2*)&bias[col0 + dcol];
            vt[(dcol+0)*128 + lloc]   = __float2half_rn(o[j][0]+bb.x);
            vt[(dcol+1)*128 + lloc]   = __float2half_rn(o[j][1]+bb.y);
            vt[(dcol+0)*128 + lloc+8] = __float2half_rn(o[j][2]+bb.x);
            vt[(dcol+1)*128 + lloc+8] = __float2half_rn(o[j][3]+bb.y);
        }
        __syncthreads();
        const int l0 = row0 & 2047;
        #pragma unroll
        for (int i=0;i<4;i++){
            int e = tid + (i<<8);           // 0..1023 uint4s; row = 16 uint4
            int d = e>>4, j16 = e&15;
            uint4 v = ((const uint4*)vt)[e];
            *(uint4*)((char*)g_Vth + (((size_t)(bh*HDIM + d))*LSEQ + l0)*2 + j16*16) = v;
        }
    }
}

// Output projection: CTX(fp16) @ Wo + bo -> d_out fp32. 128x128 tile.
__global__ __launch_bounds__(256,2)
void gemm_out(const float* __restrict__ bo, float* __restrict__ C)
{
    extern __shared__ __align__(128) char smem[];
    const uint32_t sb = (uint32_t)__cvta_generic_to_shared(smem);
    const int tid = threadIdx.x, lane = tid&31, wid = tid>>5;
    const int row0 = blockIdx.x<<7;
    const int col0 = blockIdx.y<<7;
    const int wrow = 3*DM + col0;

    float o[16][4];
    #pragma unroll
    for (int j=0;j<16;j++){ o[j][0]=0.f;o[j][1]=0.f;o[j][2]=0.f;o[j][3]=0.f; }

    gemm_mma_core<128>(sb, (const char*)g_CXh, row0, wrow, o);

    const int r = row0 + (wid<<4) + (lane>>2);
    #pragma unroll
    for (int j=0;j<16;j++){
        int dcol = 8*j + ((lane&3)<<1);
        float2 bb = *(const float2*)&bo[col0 + dcol];
        *(float2*)&C[(size_t)r*DOUT + col0 + dcol]     = make_float2(o[j][0]+bb.x, o[j][1]+bb.y);
        *(float2*)&C[(size_t)(r+8)*DOUT + col0 + dcol] = make_float2(o[j][2]+bb.x, o[j][3]+bb.y);
    }
}

// ===========================================================================
// Warp-MMA flash attention, streamed per 16-key chunk:
//   for kc: S_kc (8 MMAs) -> exp (8) -> PV_kc (8 MMAs)
// SMEM: QH 0 (16K) | KV buf0 @16K (KH 8K, VH 8K) | buf1 @32K = 48K total.
// ===========================================================================
#define SQH 0
#define KVB 16384
#define KH_O 0
#define VH_O 8192
#define ATTN_SMEM 49152

__device__ __forceinline__ void attn_stage_kv(
    uint32_t sb, uint32_t buf, size_t bhb, int k0,
    const char* gkh, const char* gvh)
{
    const int tid = threadIdx.x;
    #pragma unroll
    for (int i=0;i<4;i++){
        int idx = tid + (i<<8);
        int arr = idx>>9, c = idx&511, row = c>>3, j = c&7;
        const char* s; uint32_t off;
        if (arr==0){ s = gkh + bhb + (size_t)(k0+row)*128 + j*16; off = KH_O; }
        else       { s = gvh + bhb + (size_t)row*4096 + k0*2 + j*16; off = VH_O; }
        cpa16(sb + buf + off + swz(row*128 + j*16), s);
    }
}

__global__ __launch_bounds__(256,2)
void attn_mma()
{
    extern __shared__ __align__(128) char smem[];
    const uint32_t sb = (uint32_t)__cvta_generic_to_shared(smem);
    const int tid = threadIdx.x, lane = tid&31, wid = tid>>5;
    const int q0 = blockIdx.x<<7;
    const int bh = blockIdx.y;

    const char* gqh = (const char*)g_Qh;
    const char* gkh = (const char*)g_Kh;
    const char* gvh = (const char*)g_Vth;
    const size_t bhb = (size_t)bh*LSEQ*HDIM*2;

    // stage Q + tile0
    #pragma unroll
    for (int i=0;i<4;i++){
        int idx = tid + (i<<8);
        int row = idx>>3, j = idx&7;
        const char* s = gqh + bhb + (size_t)(q0+row)*128 + j*16;
        cpa16(sb + SQH + swz(row*128 + j*16), s);
    }
    attn_stage_kv(sb, KVB, bhb, 0, gkh, gvh);
    CPCOMMIT();
    cpwait<0>();
    __syncthreads();

    const int qr0 = wid<<4;
    const uint32_t lrow = (uint32_t)(lane&15)*128 + (uint32_t)(lane&16);
    uint32_t qh[4][4];
    #pragma unroll
    for (int c=0;c<4;c++)
        ldsm4(qh[c][0],qh[c][1],qh[c][2],qh[c][3],
              sb + SQH + swz((uint32_t)qr0*128 + lrow + c*32));

    float o[8][4];
    #pragma unroll
    for (int j=0;j<8;j++){ o[j][0]=0.f;o[j][1]=0.f;o[j][2]=0.f;o[j][3]=0.f; }
    float lsum0 = 0.f, lsum1 = 0.f;

    #pragma unroll 1
    for (int kt = 0; kt < LSEQ/64; kt++) {
        const uint32_t buf = KVB + ((uint32_t)(kt&1)<<14);
        if (kt < LSEQ/64 - 1) {
            attn_stage_kv(sb, KVB + ((uint32_t)((kt+1)&1)<<14), bhb, (kt+1)<<6, gkh, gvh);
            CPCOMMIT();
        }
        if (kt > 0) {
            if (kt < LSEQ/64 - 1) cpwait<1>(); else cpwait<0>();
            __syncthreads();
        }

        // ---- streamed: per 16-key chunk kc: S -> exp -> PV ----
        #pragma unroll
        for (int kc=0; kc<4; kc++){
            float s0[4] = {0.f,0.f,0.f,0.f};
            float s1[4] = {0.f,0.f,0.f,0.f};
            #pragma unroll
            for (int c=0;c<4;c++){
                uint32_t kh0,kh1,kh2,kh3;
                uint32_t boff = swz((uint32_t)(kc<<11) + lrow + c*32);
                ldsm4(kh0,kh1,kh2,kh3, sb + buf + KH_O + boff);
                mma_f16(s0, qh[c], kh0, kh2);
                mma_f16(s1, qh[c], kh1, kh3);
            }
            float e00 = ex2f(s0[0]*SCALE), e01 = ex2f(s0[1]*SCALE);
            float e02 = ex2f(s0[2]*SCALE), e03 = ex2f(s0[3]*SCALE);
            float e10 = ex2f(s1[0]*SCALE), e11 = ex2f(s1[1]*SCALE);
            float e12 = ex2f(s1[2]*SCALE), e13 = ex2f(s1[3]*SCALE);
            lsum0 += e00 + e01 + e10 + e11;
            lsum1 += e02 + e03 + e12 + e13;
            uint32_t ph[4];
            ph[0] = hpack(e00,e01);
            ph[1] = hpack(e02,e03);
            ph[2] = hpack(e10,e11);
            ph[3] = hpack(e12,e13);
            #pragma unroll
            for (int po=0;po<4;po++){
                uint32_t vh0,vh1,vh2,vh3;
                uint32_t boff = swz((uint32_t)(po<<11) + lrow + kc*32);
                ldsm4(vh0,vh1,vh2,vh3, sb + buf + VH_O + boff);
                mma_f16(o[2*po],   ph, vh0, vh2);
                mma_f16(o[2*po+1], ph, vh1, vh3);
            }
        }
        __syncthreads();
    }

    lsum0 += __shfl_xor_sync(0xffffffffu, lsum0, 1);
    lsum0 += __shfl_xor_sync(0xffffffffu, lsum0, 2);
    lsum1 += __shfl_xor_sync(0xffffffffu, lsum1, 1);
    lsum1 += __shfl_xor_sync(0xffffffffu, lsum1, 2);
    const float inv0 = 1.0f/lsum0, inv1 = 1.0f/lsum1;

    const int b = bh>>2, h = bh&3;
    const int r0 = q0 + qr0 + (lane>>2);
    uint32_t* ch = (uint32_t*)g_CXh;
    #pragma unroll
    for (int j=0;j<8;j++){
        int dcol = 8*j + ((lane&3)<<1);
        size_t p0 = (((size_t)(b*LSEQ + r0))*DM + h*HDIM + dcol)>>1;
        size_t p1 = (((size_t)(b*LSEQ + r0+8))*DM + h*HDIM + dcol)>>1;
        ch[p0] = hpack(o[j][0]*inv0, o[j][1]*inv0);
        ch[p1] = hpack(o[j][2]*inv1, o[j][3]*inv1);
    }
}

// ---------------------------------------------------------------------------
extern "C" void kernel_launch(void* const* d_in, const int* in_sizes, int n_in,
                              void* d_out, int out_size)
{
    const float* x  = (const float*)d_in[0];
    const float* Wq = (const float*)d_in[1];
    const float* bq = (const float*)d_in[2];
    const float* Wk = (const float*)d_in[3];
    const float* bk = (const float*)d_in[4];
    const float* Wv = (const float*)d_in[5];
    const float* bv = (const float*)d_in[6];
    const float* Wo = (const float*)d_in[7];
    const float* bo = (const float*)d_in[8];
    float* out = (float*)d_out;

    xcvt<<<2048, 256>>>(x);
    wsplit<<<112, 256>>>(Wq, Wk, Wv, Wo);

    cudaFuncSetAttribute(gemm_qkv, cudaFuncAttributeMaxDynamicSharedMemorySize, GEMM_SMEM_QKV);
    gemm_qkv<<<dim3(NTOK/128, 12), 256, GEMM_SMEM_QKV>>>(bq, bk, bv);

    cudaFuncSetAttribute(attn_mma, cudaFuncAttributeMaxDynamicSharedMemorySize, ATTN_SMEM);
    attn_mma<<<dim3(LSEQ/128, NBH), 256, ATTN_SMEM>>>();

    cudaFuncSetAttribute(gemm_out, cudaFuncAttributeMaxDynamicSharedMemorySize, GEMM_SMEM_OUT);
    gemm_out<<<dim3(NTOK/128, DOUT/128), 256, GEMM_SMEM_OUT>>>(bo, out);
}

// round 13
// speedup vs baseline: 1.0891x; 1.0891x over previous
#include <cuda_runtime.h>
#include <cuda_fp16.h>
#include <stdint.h>

typedef unsigned long long u64;

#define LSEQ 2048
#define BATCH 8
#define NH 4
#define NBH (BATCH*NH)      // 32
#define HDIM 64
#define DM 256
#define DOUT 1024
#define NTOK (BATCH*LSEQ)   // 16384
#define SCALE 0.090168440055560214f   // log2(e)/16
#define ONES2 0x3C003C00u              // half2 {1,1}

// ---------------- device scratch (no runtime alloc allowed) ----------------
__device__ __align__(16) unsigned short g_Qh[(size_t)NBH*LSEQ*HDIM];  // fp16 Q, pre-scaled by log2e/16
__device__ __align__(16) unsigned short g_Kh[(size_t)NBH*LSEQ*HDIM];  // fp16 K
__device__ __align__(16) unsigned short g_Vth[(size_t)NBH*HDIM*LSEQ]; // fp16 [bh][d][l]
__device__ __align__(16) unsigned short g_xh[(size_t)NTOK*DM];        // fp16 x
__device__ __align__(16) unsigned short g_CXh[(size_t)NTOK*DM];       // fp16 ctx [b,l,h*64+j]
#define WROWS (3*DM + DOUT)   // 1792 rows of W^T (qkv then out)
__device__ __align__(16) unsigned short g_Wh[(size_t)WROWS*DM];       // fp16 W^T [n][k]

// ---------------- scalar helpers ----------------
__device__ __forceinline__ uint32_t hpack(float a, float b){
    __half2 h2 = __floats2half2_rn(a, b);
    return *(uint32_t*)&h2;
}
// pack {lo, hi} from two f32 in one instruction
__device__ __forceinline__ uint32_t cvt_h2(float lo, float hi){
    uint32_t r; asm("cvt.rn.f16x2.f32 %0,%1,%2;":"=r"(r):"f"(hi),"f"(lo)); return r; }
__device__ __forceinline__ uint32_t h2exp2(uint32_t x){
    uint32_t r; asm("ex2.approx.f16x2 %0,%1;":"=r"(r):"r"(x)); return r; }

// ---------------- warp-MMA + cp.async primitives ----------------
__device__ __forceinline__ void ldsm4(uint32_t &r0, uint32_t &r1, uint32_t &r2, uint32_t &r3, uint32_t addr){
    asm volatile("ldmatrix.sync.aligned.m8n8.x4.shared.b16 {%0,%1,%2,%3},[%4];"
        : "=r"(r0),"=r"(r1),"=r"(r2),"=r"(r3) : "r"(addr));
}
__device__ __forceinline__ void mma_f16(float* d, const uint32_t* a, uint32_t b0, uint32_t b1){
    asm volatile("mma.sync.aligned.m16n8k16.row.col.f32.f16.f16.f32 "
        "{%0,%1,%2,%3},{%4,%5,%6,%7},{%8,%9},{%0,%1,%2,%3};"
        : "+f"(d[0]),"+f"(d[1]),"+f"(d[2]),"+f"(d[3])
        : "r"(a[0]),"r"(a[1]),"r"(a[2]),"r"(a[3]),"r"(b0),"r"(b1));
}
__device__ __forceinline__ uint32_t swz(uint32_t o){ return o ^ ((o>>3)&0x70u); }
__device__ __forceinline__ void cpa16(uint32_t saddr, const void* g){
    asm volatile("cp.async.cg.shared.global [%0],[%1],16;"::"r"(saddr),"l"(g));
}
#define CPCOMMIT() asm volatile("cp.async.commit_group;":::"memory")
template<int N> __device__ __forceinline__ void cpwait(){
    asm volatile("cp.async.wait_group %0;"::"n"(N):"memory");
}

// ===========================================================================
// Prep kernels
// ===========================================================================
__global__ __launch_bounds__(256)
void xcvt(const float* __restrict__ x)
{
    uint32_t* xh = (uint32_t*)g_xh;
    size_t p0 = (size_t)blockIdx.x*1024 + threadIdx.x;
    #pragma unroll
    for (int i=0;i<4;i++){
        size_t p = p0 + (size_t)i*256;
        float2 v = ((const float2*)x)[p];
        xh[p] = hpack(v.x, v.y);
    }
}

// W^T convert (fp16). qkv (3 x 256x256) then Wo (256x1024) -> [n][k].
__global__ __launch_bounds__(256)
void wsplit(const float* __restrict__ Wq, const float* __restrict__ Wk,
            const float* __restrict__ Wv, const float* __restrict__ Wo)
{
    __shared__ float ts[64][65];
    const int tid = threadIdx.x;
    int bx = blockIdx.x;
    const float* W; int N, kt0, nt0, rowbase;
    if (bx < 48) {
        int mat = bx/16, t = bx%16;
        W = (mat==0)?Wq:(mat==1)?Wk:Wv; N = DM;
        kt0 = (t>>2)<<6; nt0 = (t&3)<<6; rowbase = mat*DM + nt0;
    } else {
        bx -= 48;
        W = Wo; N = DOUT;
        kt0 = (bx&3)<<6; nt0 = (bx>>2)<<6; rowbase = 3*DM + nt0;
    }
    #pragma unroll
    for (int i=0;i<16;i++){
        int e = tid + (i<<8);
        int k = e>>6, n = e&63;
        ts[n][k] = W[(size_t)(kt0+k)*N + nt0 + n];
    }
    __syncthreads();
    uint32_t* wh = (uint32_t*)g_Wh;
    #pragma unroll
    for (int i=0;i<8;i++){
        int e = tid + (i<<8);
        int n = e>>5, kp = e&31;
        size_t o = (size_t)(rowbase+n)*(DM/2) + (kt0>>1) + kp;
        wh[o] = hpack(ts[n][kp*2], ts[n][kp*2+1]);
    }
}

// ===========================================================================
// HMMA GEMM core, templated on N-tile. 128(M) rows, K=256 in 4 chunks.
// ===========================================================================
template<int NT> struct GOff {
    static constexpr uint32_t AH  = 0;
    static constexpr uint32_t WH  = 16384;
    static constexpr uint32_t BUF = 16384u + (uint32_t)NT*256u;
};

template<int NT>
__device__ __forceinline__ void gemm_stage(
    uint32_t sb, uint32_t buf, const char* gah, int row0, int wrow, int kt)
{
    const int tid = threadIdx.x;
    const char* gwh = (const char*)g_Wh;
    #pragma unroll
    for (int i=0;i<4;i++){
        int idx = tid + (i<<8);
        int row = idx>>3, j = idx&7;
        const char* s = gah + (size_t)(row0+row)*512 + kt*128 + j*16;
        cpa16(sb + buf + GOff<NT>::AH + swz(row*128 + j*16), s);
    }
    #pragma unroll
    for (int i=0;i<NT/32;i++){
        int idx = tid + (i<<8);
        int row = idx>>3, j = idx&7;
        const char* s = gwh + (size_t)(wrow+row)*512 + kt*128 + j*16;
        cpa16(sb + buf + GOff<NT>::WH + swz(row*128 + j*16), s);
    }
}

template<int NT>
__device__ __forceinline__ void gemm_mma_core(
    uint32_t sb, const char* gah, int row0, int wrow, float (&o)[NT/8][4])
{
    const int tid = threadIdx.x, lane = tid&31, wid = tid>>5;
    const uint32_t lrow = (uint32_t)(lane&15)*128 + (uint32_t)(lane&16);

    gemm_stage<NT>(sb, 0, gah, row0, wrow, 0);
    CPCOMMIT();

    #pragma unroll 1
    for (int kt = 0; kt < 4; kt++) {
        const uint32_t buf = (kt&1) ? GOff<NT>::BUF : 0;
        if (kt < 3) {
            gemm_stage<NT>(sb, (kt&1)?0:GOff<NT>::BUF, gah, row0, wrow, kt+1);
            CPCOMMIT();
            cpwait<1>();
        } else {
            cpwait<0>();
        }
        __syncthreads();

        const uint32_t abase = sb + buf + (uint32_t)(wid<<4)*128;
        #pragma unroll
        for (int c=0;c<4;c++){
            uint32_t ah[4];
            ldsm4(ah[0],ah[1],ah[2],ah[3], abase + GOff<NT>::AH + swz(lrow + c*32));
            #pragma unroll
            for (int p=0;p<NT/16;p++){
                uint32_t wh0,wh1,wh2,wh3;
                uint32_t boff = swz((uint32_t)(p<<11) + lrow + c*32);
                ldsm4(wh0,wh1,wh2,wh3, sb + buf + GOff<NT>::WH + boff);
                mma_f16(o[2*p],   ah, wh0, wh2);
                mma_f16(o[2*p+1], ah, wh1, wh3);
            }
        }
        __syncthreads();
    }
}

#define GEMM_SMEM_QKV (2*(16384+64*256))     // 65536
#define GEMM_SMEM_OUT (2*(16384+128*256))    // 98304

// QKV projection: Q(pre-scaled)/K -> fp16 [bh][l][d]; V -> fp16 [bh][d][l] (fused T)
__global__ __launch_bounds__(256,2)
void gemm_qkv(const float* __restrict__ bq, const float* __restrict__ bk,
              const float* __restrict__ bv)
{
    extern __shared__ __align__(128) char smem[];
    const uint32_t sb = (uint32_t)__cvta_generic_to_shared(smem);
    const int tid = threadIdx.x, lane = tid&31, wid = tid>>5;
    const int row0 = blockIdx.x<<7;
    const int yy = blockIdx.y, mat = yy>>2, h = yy&3;
    const int col0 = h<<6;
    const float* bias = (mat==0)?bq:(mat==1)?bk:bv;
    const int wrow = mat*DM + col0;

    float o[8][4];
    #pragma unroll
    for (int j=0;j<8;j++){ o[j][0]=0.f;o[j][1]=0.f;o[j][2]=0.f;o[j][3]=0.f; }

    gemm_mma_core<64>(sb, (const char*)g_xh, row0, wrow, o);

    const int r = row0 + (wid<<4) + (lane>>2);
    const int b = r>>11, l = r&2047;
    const int bh = b*NH + h;

    if (mat < 2) {
        uint32_t* dh = (uint32_t*)((mat==0)?g_Qh:g_Kh);
        const float scl = (mat==0) ? SCALE : 1.0f;   // fold log2e/16 into Q
        #pragma unroll
        for (int j=0;j<8;j++){
            int dcol = 8*j + ((lane&3)<<1);
            float2 bb = *(const float2*)&bias[col0 + dcol];
            size_t p0 = (((size_t)bh*LSEQ + l)*HDIM + dcol)>>1;
            size_t p1 = (((size_t)bh*LSEQ + l+8)*HDIM + dcol)>>1;
            dh[p0] = hpack((o[j][0]+bb.x)*scl, (o[j][1]+bb.y)*scl);
            dh[p1] = hpack((o[j][2]+bb.x)*scl, (o[j][3]+bb.y)*scl);
        }
    } else {
        // fused V transpose: stage fp16 into smem vt[64 d][128 l] then coalesced out
        __half* vt = (__half*)smem;      // 64*128 halves = 16 KB
        const int lloc = (wid<<4) + (lane>>2);
        #pragma unroll
        for (int j=0;j<8;j++){
            int dcol = 8*j + ((lane&3)<<1);
            float2 bb = *(const float2*)&bias[col0 + dcol];
            vt[(dcol+0)*128 + lloc]   = __float2half_rn(o[j][0]+bb.x);
            vt[(dcol+1)*128 + lloc]   = __float2half_rn(o[j][1]+bb.y);
            vt[(dcol+0)*128 + lloc+8] = __float2half_rn(o[j][2]+bb.x);
            vt[(dcol+1)*128 + lloc+8] = __float2half_rn(o[j][3]+bb.y);
        }
        __syncthreads();
        const int l0 = row0 & 2047;
        #pragma unroll
        for (int i=0;i<4;i++){
            int e = tid + (i<<8);           // 0..1023 uint4s; row = 16 uint4
            int d = e>>4, j16 = e&15;
            uint4 v = ((const uint4*)vt)[e];
            *(uint4*)((char*)g_Vth + (((size_t)(bh*HDIM + d))*LSEQ + l0)*2 + j16*16) = v;
        }
    }
}

// Output projection: CTX(fp16) @ Wo + bo -> d_out fp32. 128x128 tile.
__global__ __launch_bounds__(256,2)
void gemm_out(const float* __restrict__ bo, float* __restrict__ C)
{
    extern __shared__ __align__(128) char smem[];
    const uint32_t sb = (uint32_t)__cvta_generic_to_shared(smem);
    const int tid = threadIdx.x, lane = tid&31, wid = tid>>5;
    const int row0 = blockIdx.x<<7;
    const int col0 = blockIdx.y<<7;
    const int wrow = 3*DM + col0;

    float o[16][4];
    #pragma unroll
    for (int j=0;j<16;j++){ o[j][0]=0.f;o[j][1]=0.f;o[j][2]=0.f;o[j][3]=0.f; }

    gemm_mma_core<128>(sb, (const char*)g_CXh, row0, wrow, o);

    const int r = row0 + (wid<<4) + (lane>>2);
    #pragma unroll
    for (int j=0;j<16;j++){
        int dcol = 8*j + ((lane&3)<<1);
        float2 bb = *(const float2*)&bo[col0 + dcol];
        *(float2*)&C[(size_t)r*DOUT + col0 + dcol]     = make_float2(o[j][0]+bb.x, o[j][1]+bb.y);
        *(float2*)&C[(size_t)(r+8)*DOUT + col0 + dcol] = make_float2(o[j][2]+bb.x, o[j][3]+bb.y);
    }
}

// ===========================================================================
// Warp-MMA flash attention. Per 16-key chunk: S (8 MMA) -> h2 exp2 (4 cvt +
// 4 ex2.f16x2, result IS the A-frag) -> PV (8 MMA) + rowsum ones-MMA (1).
// SMEM: QH 0 (16K) | KV buf0 @16K (KH 8K, VH 8K) | buf1 @32K = 48K total.
// ===========================================================================
#define SQH 0
#define KVB 16384
#define KH_O 0
#define VH_O 8192
#define ATTN_SMEM 49152

__device__ __forceinline__ void attn_stage_kv(
    uint32_t sb, uint32_t buf, size_t bhb, int k0,
    const char* gkh, const char* gvh)
{
    const int tid = threadIdx.x;
    #pragma unroll
    for (int i=0;i<4;i++){
        int idx = tid + (i<<8);
        int arr = idx>>9, c = idx&511, row = c>>3, j = c&7;
        const char* s; uint32_t off;
        if (arr==0){ s = gkh + bhb + (size_t)(k0+row)*128 + j*16; off = KH_O; }
        else       { s = gvh + bhb + (size_t)row*4096 + k0*2 + j*16; off = VH_O; }
        cpa16(sb + buf + off + swz(row*128 + j*16), s);
    }
}

__global__ __launch_bounds__(256,2)
void attn_mma()
{
    extern __shared__ __align__(128) char smem[];
    const uint32_t sb = (uint32_t)__cvta_generic_to_shared(smem);
    const int tid = threadIdx.x, lane = tid&31, wid = tid>>5;
    const int q0 = blockIdx.x<<7;
    const int bh = blockIdx.y;

    const char* gqh = (const char*)g_Qh;
    const char* gkh = (const char*)g_Kh;
    const char* gvh = (const char*)g_Vth;
    const size_t bhb = (size_t)bh*LSEQ*HDIM*2;

    // stage Q + tile0
    #pragma unroll
    for (int i=0;i<4;i++){
        int idx = tid + (i<<8);
        int row = idx>>3, j = idx&7;
        const char* s = gqh + bhb + (size_t)(q0+row)*128 + j*16;
        cpa16(sb + SQH + swz(row*128 + j*16), s);
    }
    attn_stage_kv(sb, KVB, bhb, 0, gkh, gvh);
    CPCOMMIT();
    cpwait<0>();
    __syncthreads();

    const int qr0 = wid<<4;
    const uint32_t lrow = (uint32_t)(lane&15)*128 + (uint32_t)(lane&16);
    uint32_t qh[4][4];
    #pragma unroll
    for (int c=0;c<4;c++)
        ldsm4(qh[c][0],qh[c][1],qh[c][2],qh[c][3],
              sb + SQH + swz((uint32_t)qr0*128 + lrow + c*32));

    float o[8][4];
    #pragma unroll
    for (int j=0;j<8;j++){ o[j][0]=0.f;o[j][1]=0.f;o[j][2]=0.f;o[j][3]=0.f; }
    float sum_acc[4] = {0.f,0.f,0.f,0.f};   // rowsum via ones-MMA (exact fp32)

    #pragma unroll 1
    for (int kt = 0; kt < LSEQ/64; kt++) {
        const uint32_t buf = KVB + ((uint32_t)(kt&1)<<14);
        if (kt < LSEQ/64 - 1) {
            attn_stage_kv(sb, KVB + ((uint32_t)((kt+1)&1)<<14), bhb, (kt+1)<<6, gkh, gvh);
            CPCOMMIT();
        }
        if (kt > 0) {
            if (kt < LSEQ/64 - 1) cpwait<1>(); else cpwait<0>();
            __syncthreads();
        }

        #pragma unroll
        for (int kc=0; kc<4; kc++){
            float s0[4] = {0.f,0.f,0.f,0.f};
            float s1[4] = {0.f,0.f,0.f,0.f};
            #pragma unroll
            for (int c=0;c<4;c++){
                uint32_t kh0,kh1,kh2,kh3;
                uint32_t boff = swz((uint32_t)(kc<<11) + lrow + c*32);
                ldsm4(kh0,kh1,kh2,kh3, sb + buf + KH_O + boff);
                mma_f16(s0, qh[c], kh0, kh2);
                mma_f16(s1, qh[c], kh1, kh3);
            }
            // exp2 in fp16x2: output IS the packed A-fragment
            uint32_t ph[4];
            ph[0] = h2exp2(cvt_h2(s0[0], s0[1]));   // (row,   k..k+1)
            ph[1] = h2exp2(cvt_h2(s0[2], s0[3]));   // (row+8, k..k+1)
            ph[2] = h2exp2(cvt_h2(s1[0], s1[1]));   // (row,   k+8..k+9)
            ph[3] = h2exp2(cvt_h2(s1[2], s1[3]));   // (row+8, k+8..k+9)
            // rowsum via ones-MMA (accumulates across all kc, kt)
            mma_f16(sum_acc, ph, ONES2, ONES2);
            #pragma unroll
            for (int po=0;po<4;po++){
                uint32_t vh0,vh1,vh2,vh3;
                uint32_t boff = swz((uint32_t)(po<<11) + lrow + kc*32);
                ldsm4(vh0,vh1,vh2,vh3, sb + buf + VH_O + boff);
                mma_f16(o[2*po],   ph, vh0, vh2);
                mma_f16(o[2*po+1], ph, vh1, vh3);
            }
        }
        __syncthreads();
    }

    const float inv0 = 1.0f/sum_acc[0], inv1 = 1.0f/sum_acc[2];

    const int b = bh>>2, h = bh&3;
    const int r0 = q0 + qr0 + (lane>>2);
    uint32_t* ch = (uint32_t*)g_CXh;
    #pragma unroll
    for (int j=0;j<8;j++){
        int dcol = 8*j + ((lane&3)<<1);
        size_t p0 = (((size_t)(b*LSEQ + r0))*DM + h*HDIM + dcol)>>1;
        size_t p1 = (((size_t)(b*LSEQ + r0+8))*DM + h*HDIM + dcol)>>1;
        ch[p0] = hpack(o[j][0]*inv0, o[j][1]*inv0);
        ch[p1] = hpack(o[j][2]*inv1, o[j][3]*inv1);
    }
}

// ---------------------------------------------------------------------------
extern "C" void kernel_launch(void* const* d_in, const int* in_sizes, int n_in,
                              void* d_out, int out_size)
{
    const float* x  = (const float*)d_in[0];
    const float* Wq = (const float*)d_in[1];
    const float* bq = (const float*)d_in[2];
    const float* Wk = (const float*)d_in[3];
    const float* bk = (const float*)d_in[4];
    const float* Wv = (const float*)d_in[5];
    const float* bv = (const float*)d_in[6];
    const float* Wo = (const float*)d_in[7];
    const float* bo = (const float*)d_in[8];
    float* out = (float*)d_out;

    xcvt<<<2048, 256>>>(x);
    wsplit<<<112, 256>>>(Wq, Wk, Wv, Wo);

    cudaFuncSetAttribute(gemm_qkv, cudaFuncAttributeMaxDynamicSharedMemorySize, GEMM_SMEM_QKV);
    gemm_qkv<<<dim3(NTOK/128, 12), 256, GEMM_SMEM_QKV>>>(bq, bk, bv);

    cudaFuncSetAttribute(attn_mma, cudaFuncAttributeMaxDynamicSharedMemorySize, ATTN_SMEM);
    attn_mma<<<dim3(LSEQ/128, NBH), 256, ATTN_SMEM>>>();

    cudaFuncSetAttribute(gemm_out, cudaFuncAttributeMaxDynamicSharedMemorySize, GEMM_SMEM_OUT);
    gemm_out<<<dim3(NTOK/128, DOUT/128), 256, GEMM_SMEM_OUT>>>(bo, out);
}

// round 14
// speedup vs baseline: 1.1292x; 1.0368x over previous
#include <cuda_runtime.h>
#include <cuda_fp16.h>
#include <stdint.h>

typedef unsigned long long u64;

#define LSEQ 2048
#define BATCH 8
#define NH 4
#define NBH (BATCH*NH)      // 32
#define HDIM 64
#define DM 256
#define DOUT 1024
#define NTOK (BATCH*LSEQ)   // 16384
#define SCALE 0.090168440055560214f   // log2(e)/16
#define ONES2 0x3C003C00u              // half2 {1,1}

// ---------------- device scratch (no runtime alloc allowed) ----------------
__device__ __align__(16) unsigned short g_Qh[(size_t)NBH*LSEQ*HDIM];  // fp16 Q, pre-scaled by log2e/16
__device__ __align__(16) unsigned short g_Kh[(size_t)NBH*LSEQ*HDIM];  // fp16 K
__device__ __align__(16) unsigned short g_Vth[(size_t)NBH*HDIM*LSEQ]; // fp16 [bh][d][l]
__device__ __align__(16) unsigned short g_xh[(size_t)NTOK*DM];        // fp16 x
__device__ __align__(16) unsigned short g_CXh[(size_t)NTOK*DM];       // fp16 ctx [b,l,h*64+j]
#define WROWS (3*DM + DOUT)   // 1792 rows of W^T (qkv then out)
__device__ __align__(16) unsigned short g_Wh[(size_t)WROWS*DM];       // fp16 W^T [n][k]

// ---------------- scalar helpers ----------------
__device__ __forceinline__ uint32_t hpack(float a, float b){
    __half2 h2 = __floats2half2_rn(a, b);
    return *(uint32_t*)&h2;
}
__device__ __forceinline__ uint32_t cvt_h2(float lo, float hi){
    uint32_t r; asm("cvt.rn.f16x2.f32 %0,%1,%2;":"=r"(r):"f"(hi),"f"(lo)); return r; }
__device__ __forceinline__ uint32_t h2exp2(uint32_t x){
    uint32_t r; asm("ex2.approx.f16x2 %0,%1;":"=r"(r):"r"(x)); return r; }

// ---------------- warp-MMA + cp.async primitives ----------------
__device__ __forceinline__ void ldsm4(uint32_t &r0, uint32_t &r1, uint32_t &r2, uint32_t &r3, uint32_t addr){
    asm volatile("ldmatrix.sync.aligned.m8n8.x4.shared.b16 {%0,%1,%2,%3},[%4];"
        : "=r"(r0),"=r"(r1),"=r"(r2),"=r"(r3) : "r"(addr));
}
__device__ __forceinline__ void mma_f16(float* d, const uint32_t* a, uint32_t b0, uint32_t b1){
    asm volatile("mma.sync.aligned.m16n8k16.row.col.f32.f16.f16.f32 "
        "{%0,%1,%2,%3},{%4,%5,%6,%7},{%8,%9},{%0,%1,%2,%3};"
        : "+f"(d[0]),"+f"(d[1]),"+f"(d[2]),"+f"(d[3])
        : "r"(a[0]),"r"(a[1]),"r"(a[2]),"r"(a[3]),"r"(b0),"r"(b1));
}
__device__ __forceinline__ uint32_t swz(uint32_t o){ return o ^ ((o>>3)&0x70u); }
__device__ __forceinline__ void cpa16(uint32_t saddr, const void* g){
    asm volatile("cp.async.cg.shared.global [%0],[%1],16;"::"r"(saddr),"l"(g));
}
#define CPCOMMIT() asm volatile("cp.async.commit_group;":::"memory")
template<int N> __device__ __forceinline__ void cpwait(){
    asm volatile("cp.async.wait_group %0;"::"n"(N):"memory");
}

// ===========================================================================
// Prep (merged): blocks [0,2048) convert x; blocks [2048,2160) convert W^T
// ===========================================================================
__global__ __launch_bounds__(256)
void prep(const float* __restrict__ x,
          const float* __restrict__ Wq, const float* __restrict__ Wk,
          const float* __restrict__ Wv, const float* __restrict__ Wo)
{
    __shared__ float ts[64][65];
    const int tid = threadIdx.x;
    int bx = blockIdx.x;

    if (bx < 2048) {
        uint32_t* xh = (uint32_t*)g_xh;
        size_t p0 = (size_t)bx*1024 + tid;
        #pragma unroll
        for (int i=0;i<4;i++){
            size_t p = p0 + (size_t)i*256;
            float2 v = ((const float2*)x)[p];
            xh[p] = hpack(v.x, v.y);
        }
        return;
    }
    bx -= 2048;

    const float* W; int N, kt0, nt0, rowbase;
    if (bx < 48) {
        int mat = bx/16, t = bx%16;
        W = (mat==0)?Wq:(mat==1)?Wk:Wv; N = DM;
        kt0 = (t>>2)<<6; nt0 = (t&3)<<6; rowbase = mat*DM + nt0;
    } else {
        bx -= 48;
        W = Wo; N = DOUT;
        kt0 = (bx&3)<<6; nt0 = (bx>>2)<<6; rowbase = 3*DM + nt0;
    }
    #pragma unroll
    for (int i=0;i<16;i++){
        int e = tid + (i<<8);
        int k = e>>6, n = e&63;
        ts[n][k] = W[(size_t)(kt0+k)*N + nt0 + n];
    }
    __syncthreads();
    uint32_t* wh = (uint32_t*)g_Wh;
    #pragma unroll
    for (int i=0;i<8;i++){
        int e = tid + (i<<8);
        int n = e>>5, kp = e&31;
        size_t o = (size_t)(rowbase+n)*(DM/2) + (kt0>>1) + kp;
        wh[o] = hpack(ts[n][kp*2], ts[n][kp*2+1]);
    }
}

// ===========================================================================
// HMMA GEMM core, NT=128. 128(M) rows, K=256 in 4 chunks, double-buffered.
// Buffer: A 16K + W 16K = 32K; 2 buffers = 64K.
// ===========================================================================
#define GAH 0
#define GWH 16384
#define GBUF 32768
#define GEMM_SMEM 65536

__device__ __forceinline__ void gemm_stage(
    uint32_t sb, uint32_t buf, const char* gah, int row0, int wrow, int kt)
{
    const int tid = threadIdx.x;
    const char* gwh = (const char*)g_Wh;
    #pragma unroll
    for (int i=0;i<4;i++){
        int idx = tid + (i<<8);
        int row = idx>>3, j = idx&7;
        const char* s = gah + (size_t)(row0+row)*512 + kt*128 + j*16;
        cpa16(sb + buf + GAH + swz(row*128 + j*16), s);
    }
    #pragma unroll
    for (int i=0;i<4;i++){
        int idx = tid + (i<<8);
        int row = idx>>3, j = idx&7;
        const char* s = gwh + (size_t)(wrow+row)*512 + kt*128 + j*16;
        cpa16(sb + buf + GWH + swz(row*128 + j*16), s);
    }
}

__device__ __forceinline__ void gemm_mma_core(
    uint32_t sb, const char* gah, int row0, int wrow, float (&o)[16][4])
{
    const int tid = threadIdx.x, lane = tid&31, wid = tid>>5;
    const uint32_t lrow = (uint32_t)(lane&15)*128 + (uint32_t)(lane&16);

    gemm_stage(sb, 0, gah, row0, wrow, 0);
    CPCOMMIT();

    #pragma unroll 1
    for (int kt = 0; kt < 4; kt++) {
        const uint32_t buf = (kt&1) ? GBUF : 0;
        if (kt < 3) {
            gemm_stage(sb, (kt&1)?0:GBUF, gah, row0, wrow, kt+1);
            CPCOMMIT();
            cpwait<1>();
        } else {
            cpwait<0>();
        }
        __syncthreads();

        const uint32_t abase = sb + buf + (uint32_t)(wid<<4)*128;
        #pragma unroll
        for (int c=0;c<4;c++){
            uint32_t ah[4];
            ldsm4(ah[0],ah[1],ah[2],ah[3], abase + GAH + swz(lrow + c*32));
            #pragma unroll
            for (int p=0;p<8;p++){
                uint32_t wh0,wh1,wh2,wh3;
                uint32_t boff = swz((uint32_t)(p<<11) + lrow + c*32);
                ldsm4(wh0,wh1,wh2,wh3, sb + buf + GWH + boff);
                mma_f16(o[2*p],   ah, wh0, wh2);
                mma_f16(o[2*p+1], ah, wh1, wh3);
            }
        }
        __syncthreads();
    }
}

// QKV projection, NT=128 (tile spans 2 heads). grid.y = 6 (2 Q, 2 K, 2 V).
__global__ __launch_bounds__(256,2)
void gemm_qkv(const float* __restrict__ bq, const float* __restrict__ bk,
              const float* __restrict__ bv)
{
    extern __shared__ __align__(128) char smem[];
    const uint32_t sb = (uint32_t)__cvta_generic_to_shared(smem);
    const int tid = threadIdx.x, lane = tid&31, wid = tid>>5;
    const int row0 = blockIdx.x<<7;
    const int yy = blockIdx.y, mat = yy>>1, col0 = (yy&1)<<7;  // col0 in {0,128}
    const float* bias = (mat==0)?bq:(mat==1)?bk:bv;
    const int wrow = mat*DM + col0;

    float o[16][4];
    #pragma unroll
    for (int j=0;j<16;j++){ o[j][0]=0.f;o[j][1]=0.f;o[j][2]=0.f;o[j][3]=0.f; }

    gemm_mma_core(sb, (const char*)g_xh, row0, wrow, o);

    const int r = row0 + (wid<<4) + (lane>>2);
    const int b = r>>11, l = r&2047;
    const int h0 = col0>>6;   // first head of this tile (0 or 2)

    if (mat < 2) {
        uint32_t* dh = (uint32_t*)((mat==0)?g_Qh:g_Kh);
        const float scl = (mat==0) ? SCALE : 1.0f;
        #pragma unroll
        for (int j=0;j<16;j++){
            int dcol = 8*j + ((lane&3)<<1);          // 0..127 within tile
            int bh = b*NH + h0 + (dcol>>6);
            int d  = dcol & 63;
            float2 bb = *(const float2*)&bias[col0 + dcol];
            size_t p0 = (((size_t)bh*LSEQ + l)*HDIM + d)>>1;
            size_t p1 = (((size_t)bh*LSEQ + l+8)*HDIM + d)>>1;
            dh[p0] = hpack((o[j][0]+bb.x)*scl, (o[j][1]+bb.y)*scl);
            dh[p1] = hpack((o[j][2]+bb.x)*scl, (o[j][3]+bb.y)*scl);
        }
    } else {
        // fused V transpose: vt[128 dcol][128 lloc] halves = 32 KB, then coalesced out
        __half* vt = (__half*)smem;
        const int lloc = (wid<<4) + (lane>>2);
        #pragma unroll
        for (int j=0;j<16;j++){
            int dcol = 8*j + ((lane&3)<<1);
            float2 bb = *(const float2*)&bias[col0 + dcol];
            vt[(dcol+0)*128 + lloc]   = __float2half_rn(o[j][0]+bb.x);
            vt[(dcol+1)*128 + lloc]   = __float2half_rn(o[j][1]+bb.y);
            vt[(dcol+0)*128 + lloc+8] = __float2half_rn(o[j][2]+bb.x);
            vt[(dcol+1)*128 + lloc+8] = __float2half_rn(o[j][3]+bb.y);
        }
        __syncthreads();
        const int l0 = row0 & 2047;
        #pragma unroll
        for (int i=0;i<8;i++){
            int e = tid + (i<<8);           // 0..2047 uint4s; row = 16 uint4
            int drow = e>>4, j16 = e&15;    // drow 0..127
            int bh = b*NH + h0 + (drow>>6);
            int d  = drow & 63;
            uint4 v = ((const uint4*)vt)[e];
            *(uint4*)((char*)g_Vth + (((size_t)bh*HDIM + d)*LSEQ + l0)*2 + j16*16) = v;
        }
    }
}

// Output projection: CTX(fp16) @ Wo + bo -> d_out fp32. 128x128 tile.
__global__ __launch_bounds__(256,2)
void gemm_out(const float* __restrict__ bo, float* __restrict__ C)
{
    extern __shared__ __align__(128) char smem[];
    const uint32_t sb = (uint32_t)__cvta_generic_to_shared(smem);
    const int tid = threadIdx.x, lane = tid&31, wid = tid>>5;
    const int row0 = blockIdx.x<<7;
    const int col0 = blockIdx.y<<7;
    const int wrow = 3*DM + col0;

    float o[16][4];
    #pragma unroll
    for (int j=0;j<16;j++){ o[j][0]=0.f;o[j][1]=0.f;o[j][2]=0.f;o[j][3]=0.f; }

    gemm_mma_core(sb, (const char*)g_CXh, row0, wrow, o);

    const int r = row0 + (wid<<4) + (lane>>2);
    #pragma unroll
    for (int j=0;j<16;j++){
        int dcol = 8*j + ((lane&3)<<1);
        float2 bb = *(const float2*)&bo[col0 + dcol];
        *(float2*)&C[(size_t)r*DOUT + col0 + dcol]     = make_float2(o[j][0]+bb.x, o[j][1]+bb.y);
        *(float2*)&C[(size_t)(r+8)*DOUT + col0 + dcol] = make_float2(o[j][2]+bb.x, o[j][3]+bb.y);
    }
}

// ===========================================================================
// Warp-MMA flash attention (unchanged from R13 — at HMMA pipe ceiling).
// ===========================================================================
#define SQH 0
#define KVB 16384
#define KH_O 0
#define VH_O 8192
#define ATTN_SMEM 49152

__device__ __forceinline__ void attn_stage_kv(
    uint32_t sb, uint32_t buf, size_t bhb, int k0,
    const char* gkh, const char* gvh)
{
    const int tid = threadIdx.x;
    #pragma unroll
    for (int i=0;i<4;i++){
        int idx = tid + (i<<8);
        int arr = idx>>9, c = idx&511, row = c>>3, j = c&7;
        const char* s; uint32_t off;
        if (arr==0){ s = gkh + bhb + (size_t)(k0+row)*128 + j*16; off = KH_O; }
        else       { s = gvh + bhb + (size_t)row*4096 + k0*2 + j*16; off = VH_O; }
        cpa16(sb + buf + off + swz(row*128 + j*16), s);
    }
}

__global__ __launch_bounds__(256,2)
void attn_mma()
{
    extern __shared__ __align__(128) char smem[];
    const uint32_t sb = (uint32_t)__cvta_generic_to_shared(smem);
    const int tid = threadIdx.x, lane = tid&31, wid = tid>>5;
    const int q0 = blockIdx.x<<7;
    const int bh = blockIdx.y;

    const char* gqh = (const char*)g_Qh;
    const char* gkh = (const char*)g_Kh;
    const char* gvh = (const char*)g_Vth;
    const size_t bhb = (size_t)bh*LSEQ*HDIM*2;

    #pragma unroll
    for (int i=0;i<4;i++){
        int idx = tid + (i<<8);
        int row = idx>>3, j = idx&7;
        const char* s = gqh + bhb + (size_t)(q0+row)*128 + j*16;
        cpa16(sb + SQH + swz(row*128 + j*16), s);
    }
    attn_stage_kv(sb, KVB, bhb, 0, gkh, gvh);
    CPCOMMIT();
    cpwait<0>();
    __syncthreads();

    const int qr0 = wid<<4;
    const uint32_t lrow = (uint32_t)(lane&15)*128 + (uint32_t)(lane&16);
    uint32_t qh[4][4];
    #pragma unroll
    for (int c=0;c<4;c++)
        ldsm4(qh[c][0],qh[c][1],qh[c][2],qh[c][3],
              sb + SQH + swz((uint32_t)qr0*128 + lrow + c*32));

    float o[8][4];
    #pragma unroll
    for (int j=0;j<8;j++){ o[j][0]=0.f;o[j][1]=0.f;o[j][2]=0.f;o[j][3]=0.f; }
    float sum_acc[4] = {0.f,0.f,0.f,0.f};

    #pragma unroll 1
    for (int kt = 0; kt < LSEQ/64; kt++) {
        const uint32_t buf = KVB + ((uint32_t)(kt&1)<<14);
        if (kt < LSEQ/64 - 1) {
            attn_stage_kv(sb, KVB + ((uint32_t)((kt+1)&1)<<14), bhb, (kt+1)<<6, gkh, gvh);
            CPCOMMIT();
        }
        if (kt > 0) {
            if (kt < LSEQ/64 - 1) cpwait<1>(); else cpwait<0>();
            __syncthreads();
        }

        #pragma unroll
        for (int kc=0; kc<4; kc++){
            float s0[4] = {0.f,0.f,0.f,0.f};
            float s1[4] = {0.f,0.f,0.f,0.f};
            #pragma unroll
            for (int c=0;c<4;c++){
                uint32_t kh0,kh1,kh2,kh3;
                uint32_t boff = swz((uint32_t)(kc<<11) + lrow + c*32);
                ldsm4(kh0,kh1,kh2,kh3, sb + buf + KH_O + boff);
                mma_f16(s0, qh[c], kh0, kh2);
                mma_f16(s1, qh[c], kh1, kh3);
            }
            uint32_t ph[4];
            ph[0] = h2exp2(cvt_h2(s0[0], s0[1]));
            ph[1] = h2exp2(cvt_h2(s0[2], s0[3]));
            ph[2] = h2exp2(cvt_h2(s1[0], s1[1]));
            ph[3] = h2exp2(cvt_h2(s1[2], s1[3]));
            mma_f16(sum_acc, ph, ONES2, ONES2);
            #pragma unroll
            for (int po=0;po<4;po++){
                uint32_t vh0,vh1,vh2,vh3;
                uint32_t boff = swz((uint32_t)(po<<11) + lrow + kc*32);
                ldsm4(vh0,vh1,vh2,vh3, sb + buf + VH_O + boff);
                mma_f16(o[2*po],   ph, vh0, vh2);
                mma_f16(o[2*po+1], ph, vh1, vh3);
            }
        }
        __syncthreads();
    }

    const float inv0 = 1.0f/sum_acc[0], inv1 = 1.0f/sum_acc[2];

    const int b = bh>>2, h = bh&3;
    const int r0 = q0 + qr0 + (lane>>2);
    uint32_t* ch = (uint32_t*)g_CXh;
    #pragma unroll
    for (int j=0;j<8;j++){
        int dcol = 8*j + ((lane&3)<<1);
        size_t p0 = (((size_t)(b*LSEQ + r0))*DM + h*HDIM + dcol)>>1;
        size_t p1 = (((size_t)(b*LSEQ + r0+8))*DM + h*HDIM + dcol)>>1;
        ch[p0] = hpack(o[j][0]*inv0, o[j][1]*inv0);
        ch[p1] = hpack(o[j][2]*inv1, o[j][3]*inv1);
    }
}

// ---------------------------------------------------------------------------
extern "C" void kernel_launch(void* const* d_in, const int* in_sizes, int n_in,
                              void* d_out, int out_size)
{
    const float* x  = (const float*)d_in[0];
    const float* Wq = (const float*)d_in[1];
    const float* bq = (const float*)d_in[2];
    const float* Wk = (const float*)d_in[3];
    const float* bk = (const float*)d_in[4];
    const float* Wv = (const float*)d_in[5];
    const float* bv = (const float*)d_in[6];
    const float* Wo = (const float*)d_in[7];
    const float* bo = (const float*)d_in[8];
    float* out = (float*)d_out;

    prep<<<2160, 256>>>(x, Wq, Wk, Wv, Wo);

    cudaFuncSetAttribute(gemm_qkv, cudaFuncAttributeMaxDynamicSharedMemorySize, GEMM_SMEM);
    gemm_qkv<<<dim3(NTOK/128, 6), 256, GEMM_SMEM>>>(bq, bk, bv);

    cudaFuncSetAttribute(attn_mma, cudaFuncAttributeMaxDynamicSharedMemorySize, ATTN_SMEM);
    attn_mma<<<dim3(LSEQ/128, NBH), 256, ATTN_SMEM>>>();

    cudaFuncSetAttribute(gemm_out, cudaFuncAttributeMaxDynamicSharedMemorySize, GEMM_SMEM);
    gemm_out<<<dim3(NTOK/128, DOUT/128), 256, GEMM_SMEM>>>(bo, out);
}